// round 12
// baseline (speedup 1.0000x reference)
#include <cuda_runtime.h>
#include <cuda_bf16.h>
#include <cstdint>
#include <math.h>

#define BSZ 8192
#define DIM 128
#define TMM 128
#define TNN 256
#define NT0 2048          // z=0 tiles (64 x 32)
#define NTILES 4096
#define GRID 148
#define TINV 14.285714285714286f
// stage: A int8 16KB @0, B int8 32KB @16384, A-scales 512B @49152, B-scales 1KB @49664
#define STAGE 51200
#define SMEM_TOTAL (2 * STAGE)

__device__ double g_partial[2][64];
__device__ signed char g_q1[BSZ * DIM];
__device__ signed char g_q2[BSZ * DIM];
__device__ float g_srowt[BSZ];   // e1 row scale * TINV
__device__ float g_scol1[BSZ];   // e1 col scale
__device__ float g_scol2[BSZ];   // e2 col scale

__device__ __forceinline__ uint32_t smem_u32(const void* p) {
    uint32_t a;
    asm("{ .reg .u64 t; cvta.to.shared.u64 t, %1; cvt.u32.u64 %0, t; }" : "=r"(a) : "l"(p));
    return a;
}
__device__ __forceinline__ void ldsm_x4(uint32_t* r, uint32_t addr) {
    asm volatile("ldmatrix.sync.aligned.m8n8.x4.shared.b16 {%0,%1,%2,%3}, [%4];"
                 : "=r"(r[0]), "=r"(r[1]), "=r"(r[2]), "=r"(r[3]) : "r"(addr));
}
__device__ __forceinline__ void imma_16832(int* d, const uint32_t* a,
                                           uint32_t b0, uint32_t b1) {
    asm volatile(
        "mma.sync.aligned.m16n8k32.row.col.s32.s8.s8.s32 "
        "{%0,%1,%2,%3}, {%4,%5,%6,%7}, {%8,%9}, {%0,%1,%2,%3};"
        : "+r"(d[0]), "+r"(d[1]), "+r"(d[2]), "+r"(d[3])
        : "r"(a[0]), "r"(a[1]), "r"(a[2]), "r"(a[3]), "r"(b0), "r"(b1));
}
#define CP_ASYNC(dst, src) \
    asm volatile("cp.async.cg.shared.global [%0], [%1], 16;" :: "r"(dst), "l"(src) : "memory")
#define CP_COMMIT() asm volatile("cp.async.commit_group;" ::: "memory")
#define CP_WAIT(n)  asm volatile("cp.async.wait_group %0;" :: "n"(n) : "memory")

// int8 tile smem: 128B rows, 8 chunks of 16B, chunk ^= row&7 (conflict-free).
__device__ __forceinline__ int soff(int row, int chunk) {
    return (row << 7) + (((chunk ^ (row & 7))) << 4);
}

// ---- loss1 tile classification: excluded k-band per row i is [i, 2i] mod B ----
__device__ __forceinline__ bool tile_skip(int r0, int c0) {
    int r1 = r0 + TMM - 1, c1 = c0 + TNN - 1;
    if (r1 < BSZ / 2) return (c0 >= r1) && (c1 <= 2 * r0);
    return (c0 >= r1) || (c1 <= 2 * r0 - BSZ);
}
__device__ __forceinline__ bool tile_full(int r0, int c0) {
    int r1 = r0 + TMM - 1, c1 = c0 + TNN - 1;
    if (r1 < BSZ / 2) return (c1 < r0) || (c0 > 2 * r1);
    return (c0 > 2 * r1 - BSZ) && (c1 < r0);
}
__device__ __forceinline__ int next_tile(int t) {
    t += GRID;
    while (t < NT0 && tile_skip((t >> 5) * TMM, (t & 31) * TNN)) t += GRID;
    return t;
}

// ---- kernel 1: fp32 normalize -> per-row int8 quant + scales ----
__global__ void prep_kernel(const float* __restrict__ e1, const float* __restrict__ e2) {
    int warp = threadIdx.x >> 5, lane = threadIdx.x & 31;
    int row = blockIdx.x * 8 + warp;
    const float* src = blockIdx.y ? e2 : e1;
    signed char* dst = blockIdx.y ? g_q2 : g_q1;
    float4 v = ((const float4*)(src + (size_t)row * DIM))[lane];
    float s = v.x * v.x + v.y * v.y + v.z * v.z + v.w * v.w;
    float am = fmaxf(fmaxf(fabsf(v.x), fabsf(v.y)), fmaxf(fabsf(v.z), fabsf(v.w)));
    #pragma unroll
    for (int o = 16; o > 0; o >>= 1) {
        s  += __shfl_xor_sync(0xffffffffu, s, o);
        am  = fmaxf(am, __shfl_xor_sync(0xffffffffu, am, o));
    }
    float inv = rsqrtf(s);
    float qs = 127.0f / am;               // q = round(x * 127 / rowmax): norm cancels
    char4 q;
    q.x = (signed char)__float2int_rn(v.x * qs);
    q.y = (signed char)__float2int_rn(v.y * qs);
    q.z = (signed char)__float2int_rn(v.z * qs);
    q.w = (signed char)__float2int_rn(v.w * qs);
    ((char4*)(dst + (size_t)row * DIM))[lane] = q;
    if (lane == 0) {
        float sc = am * inv * (1.0f / 127.0f);   // sim = acc * sc_i * sc_k
        if (blockIdx.y == 0) { g_srowt[row] = sc * TINV; g_scol1[row] = sc; }
        else                 { g_scol2[row] = sc; }
    }
    if (blockIdx.x == 0 && blockIdx.y == 0 && threadIdx.x < 128)
        ((double*)g_partial)[threadIdx.x] = 0.0;
}

// ---- prefetch one tile (A 128 rows + B 256 rows int8 + scales) ----
__device__ __forceinline__ void prefetch_tile(int t, char* buf, int tid) {
    int z = t >= NT0;
    int tt = t & (NT0 - 1);
    int i0 = (tt >> 5) * TMM, k0 = (tt & 31) * TNN;
    const signed char* Ap = g_q1 + (size_t)i0 * DIM;
    const signed char* Bp = (z ? g_q2 : g_q1) + (size_t)k0 * DIM;
    #pragma unroll
    for (int s = 0; s < 2; s++) {            // A: 1024 16B chunks
        int l = tid + s * 512, r = l >> 3, c = l & 7;
        CP_ASYNC(smem_u32(buf + soff(r, c)), (const void*)(Ap + (size_t)r * DIM + c * 16));
    }
    #pragma unroll
    for (int s = 0; s < 4; s++) {            // B: 2048 16B chunks
        int l = tid + s * 512, r = l >> 3, c = l & 7;
        CP_ASYNC(smem_u32(buf + 16384 + soff(r, c)),
                 (const void*)(Bp + (size_t)r * DIM + c * 16));
    }
    if (tid < 32) {                          // A scales: 128 floats
        CP_ASYNC(smem_u32(buf + 49152 + tid * 16), (const void*)(g_srowt + i0 + tid * 4));
    } else if (tid < 96) {                   // B scales: 256 floats
        const float* cs = (z ? g_scol2 : g_scol1) + k0;
        CP_ASYNC(smem_u32(buf + 49664 + (tid - 32) * 16), (const void*)(cs + (tid - 32) * 4));
    }
}

// ---- kernel 2: persistent double-buffered int8 IMMA GEMM + fused epilogue ----
// 512 threads, 16 warps in 4(m) x 4(n); warp tile 32 x 64; CTA tile 128 x 256.
__global__ __launch_bounds__(512, 1) void tile_kernel() {
    extern __shared__ char smem[];
    const int tid = threadIdx.x;
    const int wid = tid >> 5, lane = tid & 31;
    const int wm = (wid & 3) * 32, wn = (wid >> 2) * 64;

    int t = next_tile((int)blockIdx.x - GRID);
    if (t < NTILES) { prefetch_tile(t, smem, tid); }
    CP_COMMIT();

    float l1 = 0.0f, l2 = 0.0f;
    int cur = 0;

    while (t < NTILES) {
        int tn = next_tile(t);
        if (tn < NTILES) {
            prefetch_tile(tn, smem + (cur ^ 1) * STAGE, tid);
            CP_COMMIT();
            CP_WAIT(1);
        } else {
            CP_WAIT(0);
        }
        __syncthreads();

        char* buf = smem + cur * STAGE;
        const uint32_t sA = smem_u32(buf);
        const uint32_t sB = sA + 16384;
        const float* saS = (const float*)(buf + 49152);
        const float* sbS = (const float*)(buf + 49664);
        const int z  = t >= NT0;
        const int tt = t & (NT0 - 1);
        const int i0 = (tt >> 5) * TMM;
        const int k0 = (tt & 31) * TNN;
        const bool need_mask = (z == 0) && !tile_full(i0, k0);

        int acc[2][8][4];
        #pragma unroll
        for (int mi = 0; mi < 2; mi++)
            #pragma unroll
            for (int nj = 0; nj < 8; nj++)
                #pragma unroll
                for (int q = 0; q < 4; q++) acc[mi][nj][q] = 0;

        #pragma unroll
        for (int kk = 0; kk < 4; kk++) {     // k-chunks of 32 int8
            uint32_t a[2][4], b[4][4];
            #pragma unroll
            for (int mi = 0; mi < 2; mi++) {
                int row = wm + mi * 16 + (lane & 15);
                int chunk = kk * 2 + (lane >> 4);
                ldsm_x4(a[mi], sA + soff(row, chunk));
            }
            #pragma unroll
            for (int g = 0; g < 4; g++) {
                int row = wn + g * 16 + ((lane >> 4) << 3) + (lane & 7);
                int chunk = kk * 2 + ((lane >> 3) & 1);
                ldsm_x4(b[g], sB + soff(row, chunk));
            }
            #pragma unroll
            for (int mi = 0; mi < 2; mi++)
                #pragma unroll
                for (int nj = 0; nj < 8; nj++)
                    imma_16832(acc[mi][nj], a[mi],
                               b[nj >> 1][(nj & 1) * 2], b[nj >> 1][(nj & 1) * 2 + 1]);
        }
        __syncthreads();    // all reads of buf done; safe to overwrite next iter

        // Epilogue: sim = acc * sa(row,*TINV) * sb(col); exp; optional band mask.
        const int gID = lane >> 2, tig = lane & 3;
        float sa[4];
        #pragma unroll
        for (int mi = 0; mi < 2; mi++) {
            sa[mi * 2 + 0] = saS[wm + mi * 16 + gID];
            sa[mi * 2 + 1] = saS[wm + mi * 16 + gID + 8];
        }
        float local = 0.0f;
        #pragma unroll
        for (int mi = 0; mi < 2; mi++) {
            #pragma unroll
            for (int nj = 0; nj < 8; nj++) {
                int c0 = wn + nj * 8 + 2 * tig;
                float sb0 = sbS[c0], sb1 = sbS[c0 + 1];
                if (need_mask) {
                    int gi0 = i0 + wm + mi * 16 + gID;
                    int gk0 = k0 + c0;
                    #pragma unroll
                    for (int q = 0; q < 4; q++) {
                        int gi = gi0 + (q >> 1) * 8;
                        int gk = gk0 + (q & 1);
                        float val = (float)acc[mi][nj][q] * (sa[mi * 2 + (q >> 1)] *
                                                            ((q & 1) ? sb1 : sb0));
                        float e = __expf(val);
                        bool ok = (((gk - gi) & (BSZ - 1)) > gi);
                        local += ok ? e : 0.0f;
                    }
                } else {
                    #pragma unroll
                    for (int q = 0; q < 4; q++) {
                        float val = (float)acc[mi][nj][q] * (sa[mi * 2 + (q >> 1)] *
                                                            ((q & 1) ? sb1 : sb0));
                        local += __expf(val);
                    }
                }
            }
        }
        if (z) l2 += local; else l1 += local;

        cur ^= 1;
        t = tn;
    }

    // Final reduction: 2 atomics per CTA.
    #pragma unroll
    for (int o = 16; o > 0; o >>= 1) {
        l1 += __shfl_xor_sync(0xffffffffu, l1, o);
        l2 += __shfl_xor_sync(0xffffffffu, l2, o);
    }
    __shared__ float redA[16], redB[16];
    if (lane == 0) { redA[wid] = l1; redB[wid] = l2; }
    __syncthreads();
    if (tid == 0) {
        float s1 = 0.0f, s2 = 0.0f;
        #pragma unroll
        for (int w = 0; w < 16; w++) { s1 += redA[w]; s2 += redB[w]; }
        int slot = blockIdx.x & 63;
        atomicAdd(&g_partial[0][slot], (double)s1);
        atomicAdd(&g_partial[1][slot], (double)s2);
    }
}

__global__ void final_kernel(float* __restrict__ out) {
    double l1 = 0.0, l2 = 0.0;
    #pragma unroll
    for (int i = 0; i < 64; i++) { l1 += g_partial[0][i]; l2 += g_partial[1][i]; }
    out[0] = (float)(-log(l1 / l2));
}

extern "C" void kernel_launch(void* const* d_in, const int* in_sizes, int n_in,
                              void* d_out, int out_size) {
    const float* e1 = (const float*)d_in[0];
    const float* e2 = (const float*)d_in[1];
    float* out = (float*)d_out;

    prep_kernel<<<dim3(BSZ / 8, 2), 256>>>(e1, e2);

    cudaFuncSetAttribute(tile_kernel, cudaFuncAttributeMaxDynamicSharedMemorySize, SMEM_TOTAL);
    tile_kernel<<<GRID, 512, SMEM_TOTAL>>>();

    final_kernel<<<1, 1>>>(out);
}

// round 13
// speedup vs baseline: 2.3370x; 2.3370x over previous
#include <cuda_runtime.h>
#include <cuda_bf16.h>
#include <cstdint>
#include <math.h>

#define BSZ 8192
#define DIM 128
#define TMM 128
#define TNN 256
#define NT0 2048          // z=0 tiles (64 x 32)
#define NTILES 4096
#define GRID 148
// sqrt(log2(e)/T): rows pre-scaled so exp(sim/T) == ex2(dot)
#define PRESCALE 4.5398160190896614f
#define STAGE 98304       // 96KB per stage: A 32KB + B 64KB
#define SMEM_TOTAL (2 * STAGE)

__device__ double g_partial[2][64];
__device__ __nv_bfloat16 g_b1[BSZ * DIM];
__device__ __nv_bfloat16 g_b2[BSZ * DIM];

__device__ __forceinline__ uint32_t smem_u32(const void* p) {
    uint32_t a;
    asm("{ .reg .u64 t; cvta.to.shared.u64 t, %1; cvt.u32.u64 %0, t; }" : "=r"(a) : "l"(p));
    return a;
}
__device__ __forceinline__ void ldsm_x4(uint32_t* r, uint32_t addr) {
    asm volatile("ldmatrix.sync.aligned.m8n8.x4.shared.b16 {%0,%1,%2,%3}, [%4];"
                 : "=r"(r[0]), "=r"(r[1]), "=r"(r[2]), "=r"(r[3]) : "r"(addr));
}
__device__ __forceinline__ void mma_16816(float* d, const uint32_t* a,
                                          uint32_t b0, uint32_t b1) {
    asm volatile(
        "mma.sync.aligned.m16n8k16.row.col.f32.bf16.bf16.f32 "
        "{%0,%1,%2,%3}, {%4,%5,%6,%7}, {%8,%9}, {%0,%1,%2,%3};"
        : "+f"(d[0]), "+f"(d[1]), "+f"(d[2]), "+f"(d[3])
        : "r"(a[0]), "r"(a[1]), "r"(a[2]), "r"(a[3]), "r"(b0), "r"(b1));
}
__device__ __forceinline__ float ex2f(float x) {
    float r;
    asm("ex2.approx.f32 %0, %1;" : "=f"(r) : "f"(x));
    return r;
}
#define CP_ASYNC(dst, src) \
    asm volatile("cp.async.cg.shared.global [%0], [%1], 16;" :: "r"(dst), "l"(src) : "memory")
#define CP_COMMIT() asm volatile("cp.async.commit_group;" ::: "memory")
#define CP_WAIT(n)  asm volatile("cp.async.wait_group %0;" :: "n"(n) : "memory")

// Swizzled smem byte offset: 256B rows, 16B chunks, chunk ^= row&7.
__device__ __forceinline__ int soff(int row, int chunk) {
    return row * 256 + ((chunk ^ (row & 7)) << 4);
}

// ---- loss1 tile classification: excluded k-band per row i is [i, 2i] mod B ----
__device__ __forceinline__ bool tile_skip(int r0, int c0) {
    int r1 = r0 + TMM - 1, c1 = c0 + TNN - 1;
    if (r1 < BSZ / 2) return (c0 >= r1) && (c1 <= 2 * r0);
    return (c0 >= r1) || (c1 <= 2 * r0 - BSZ);
}
__device__ __forceinline__ bool tile_full(int r0, int c0) {
    int r1 = r0 + TMM - 1, c1 = c0 + TNN - 1;
    if (r1 < BSZ / 2) return (c1 < r0) || (c0 > 2 * r1);
    return (c0 > 2 * r1 - BSZ) && (c1 < r0);
}
__device__ __forceinline__ int next_tile(int t) {
    t += GRID;
    while (t < NT0 && tile_skip((t >> 5) * TMM, (t & 31) * TNN)) t += GRID;
    return t;
}

// ---- kernel 1: normalize rows in fp32 (x sqrt(log2e/T)), write bf16 ----
__global__ void prep_kernel(const float* __restrict__ e1, const float* __restrict__ e2) {
    int warp = threadIdx.x >> 5, lane = threadIdx.x & 31;
    int row = blockIdx.x * 8 + warp;
    const float* src = blockIdx.y ? e2 : e1;
    __nv_bfloat16* dst = blockIdx.y ? g_b2 : g_b1;
    float4 v = ((const float4*)(src + (size_t)row * DIM))[lane];
    float s = v.x * v.x + v.y * v.y + v.z * v.z + v.w * v.w;
    #pragma unroll
    for (int o = 16; o > 0; o >>= 1) s += __shfl_xor_sync(0xffffffffu, s, o);
    float inv = rsqrtf(s) * PRESCALE;
    __nv_bfloat162 p0 = __float22bfloat162_rn(make_float2(v.x * inv, v.y * inv));
    __nv_bfloat162 p1 = __float22bfloat162_rn(make_float2(v.z * inv, v.w * inv));
    ((__nv_bfloat162*)(dst + (size_t)row * DIM))[lane * 2 + 0] = p0;
    ((__nv_bfloat162*)(dst + (size_t)row * DIM))[lane * 2 + 1] = p1;
    if (blockIdx.x == 0 && blockIdx.y == 0 && threadIdx.x < 128)
        ((double*)g_partial)[threadIdx.x] = 0.0;
}

// ---- prefetch one tile (A 128 rows + B 256 rows) via cp.async ----
__device__ __forceinline__ void prefetch_tile(int t, char* buf, int tid) {
    int z = t >= NT0;
    int tt = t & (NT0 - 1);
    const __nv_bfloat16* Ap = g_b1 + (size_t)((tt >> 5) * TMM) * DIM;
    const __nv_bfloat16* Bp = (z ? g_b2 : g_b1) + (size_t)((tt & 31) * TNN) * DIM;
    #pragma unroll
    for (int s = 0; s < 4; s++) {
        int l = tid + s * 512, r = l >> 4, c = l & 15;
        CP_ASYNC(smem_u32(buf + soff(r, c)), (const void*)(Ap + (size_t)r * DIM + c * 8));
    }
    #pragma unroll
    for (int s = 0; s < 8; s++) {
        int l = tid + s * 512, r = l >> 4, c = l & 15;
        CP_ASYNC(smem_u32(buf + 32768 + soff(r, c)), (const void*)(Bp + (size_t)r * DIM + c * 8));
    }
}

// ---- kernel 2: persistent double-buffered mma.sync GEMM, nj-outer loop so
// each n-group's exp epilogue hides under the next group's HMMA stream ----
__global__ __launch_bounds__(512, 1) void tile_kernel() {
    extern __shared__ char smem[];
    const int tid = threadIdx.x;
    const int wid = tid >> 5, lane = tid & 31;
    const int wm = (wid & 3) * 32, wn = (wid >> 2) * 64;

    int t = next_tile((int)blockIdx.x - GRID);
    if (t < NTILES) { prefetch_tile(t, smem, tid); }
    CP_COMMIT();

    float l1 = 0.0f, l2 = 0.0f;
    int cur = 0;

    while (t < NTILES) {
        int tn = next_tile(t);
        if (tn < NTILES) {
            prefetch_tile(tn, smem + (cur ^ 1) * STAGE, tid);
            CP_COMMIT();
            CP_WAIT(1);
        } else {
            CP_WAIT(0);
        }
        __syncthreads();

        const uint32_t sA = smem_u32(smem + cur * STAGE);
        const uint32_t sB = sA + 32768;
        const int z  = t >= NT0;
        const int tt = t & (NT0 - 1);
        const int i0 = (tt >> 5) * TMM;
        const int k0 = (tt & 31) * TNN;
        const bool need_mask = (z == 0) && !tile_full(i0, k0);
        const int gID = lane >> 2, tig = lane & 3;

        // Load ALL A fragments up front (2 mi x 8 k-chunks x 4 regs = 64 regs).
        uint32_t a[2][8][4];
        #pragma unroll
        for (int kk = 0; kk < 8; kk++) {
            #pragma unroll
            for (int mi = 0; mi < 2; mi++) {
                int row = wm + mi * 16 + (lane & 15);
                int chunk = kk * 2 + (lane >> 4);
                ldsm_x4(a[mi][kk], sA + soff(row, chunk));
            }
        }

        float local = 0.0f;
        #pragma unroll
        for (int g = 0; g < 4; g++) {        // 4 n-groups of 16 columns
            float acc[2][2][4];
            #pragma unroll
            for (int mi = 0; mi < 2; mi++)
                #pragma unroll
                for (int jn = 0; jn < 2; jn++)
                    #pragma unroll
                    for (int q = 0; q < 4; q++) acc[mi][jn][q] = 0.0f;

            #pragma unroll
            for (int kk = 0; kk < 8; kk++) {
                uint32_t b[4];
                int row = wn + g * 16 + ((lane >> 4) << 3) + (lane & 7);
                int chunk = kk * 2 + ((lane >> 3) & 1);
                ldsm_x4(b, sB + soff(row, chunk));
                #pragma unroll
                for (int mi = 0; mi < 2; mi++)
                    #pragma unroll
                    for (int jn = 0; jn < 2; jn++)
                        mma_16816(acc[mi][jn], a[mi][kk], b[jn * 2], b[jn * 2 + 1]);
            }

            // Epilogue for this n-group: issues before group g+1's MMAs, so
            // MUFU work hides under sibling warps' tensor stream.
            if (need_mask) {
                #pragma unroll
                for (int mi = 0; mi < 2; mi++)
                    #pragma unroll
                    for (int jn = 0; jn < 2; jn++) {
                        int gi0 = i0 + wm + mi * 16 + gID;
                        int gk0 = k0 + wn + g * 16 + jn * 8 + 2 * tig;
                        #pragma unroll
                        for (int q = 0; q < 4; q++) {
                            int gi = gi0 + (q >> 1) * 8;
                            int gk = gk0 + (q & 1);
                            float e = ex2f(acc[mi][jn][q]);
                            bool ok = (((gk - gi) & (BSZ - 1)) > gi);
                            local += ok ? e : 0.0f;
                        }
                    }
            } else {
                #pragma unroll
                for (int mi = 0; mi < 2; mi++)
                    #pragma unroll
                    for (int jn = 0; jn < 2; jn++)
                        #pragma unroll
                        for (int q = 0; q < 4; q++)
                            local += ex2f(acc[mi][jn][q]);
            }
        }
        if (z) l2 += local; else l1 += local;

        __syncthreads();   // all reads of buf done before it is overwritten
        cur ^= 1;
        t = tn;
    }

    #pragma unroll
    for (int o = 16; o > 0; o >>= 1) {
        l1 += __shfl_xor_sync(0xffffffffu, l1, o);
        l2 += __shfl_xor_sync(0xffffffffu, l2, o);
    }
    __shared__ float redA[16], redB[16];
    if (lane == 0) { redA[wid] = l1; redB[wid] = l2; }
    __syncthreads();
    if (tid == 0) {
        float s1 = 0.0f, s2 = 0.0f;
        #pragma unroll
        for (int w = 0; w < 16; w++) { s1 += redA[w]; s2 += redB[w]; }
        int slot = blockIdx.x & 63;
        atomicAdd(&g_partial[0][slot], (double)s1);
        atomicAdd(&g_partial[1][slot], (double)s2);
    }
}

__global__ void final_kernel(float* __restrict__ out) {
    double l1 = 0.0, l2 = 0.0;
    #pragma unroll
    for (int i = 0; i < 64; i++) { l1 += g_partial[0][i]; l2 += g_partial[1][i]; }
    out[0] = (float)(-log(l1 / l2));
}

extern "C" void kernel_launch(void* const* d_in, const int* in_sizes, int n_in,
                              void* d_out, int out_size) {
    const float* e1 = (const float*)d_in[0];
    const float* e2 = (const float*)d_in[1];
    float* out = (float*)d_out;

    prep_kernel<<<dim3(BSZ / 8, 2), 256>>>(e1, e2);

    cudaFuncSetAttribute(tile_kernel, cudaFuncAttributeMaxDynamicSharedMemorySize, SMEM_TOTAL);
    tile_kernel<<<GRID, 512, SMEM_TOTAL>>>();

    final_kernel<<<1, 1>>>(out);
}